// round 1
// baseline (speedup 1.0000x reference)
#include <cuda_runtime.h>
#include <cstdint>
#include <cstddef>

// ---------------------------------------------------------------------------
// Fused MoE element-wise gating kernel (tf32 mma.sync, fp32 accumulate)
//   out[b,o] = sum_e softmax_e(x@Wg + bg)[b,e,o] * (L3(L2(L1(x))) + b3)[b,e,o]
// Shapes: B=65536, L=256, E=8, H1=128, H2=64, O=256, all fp32.
//
// CTA tile: 128 batch rows x 128 output cols (O split in 2).
// 512 threads = 16 warps = 8 m-tiles (m16) x 2 column groups.
// Experts processed sequentially; h1/h2 of current expert staged in SMEM.
// Gate accumulated online: acc += exp(g)*(o+b3), s += exp(g); out = acc/s.
// ---------------------------------------------------------------------------

#define BT       128
#define LDIM     256
#define ODIM     256
#define NE       8
#define H1D      128
#define H2D      64
#define EO       (NE * ODIM)     // 2048, Wg row stride
#define OC       128             // output cols per CTA
#define NTHREADS 512

#define SMEM_FLOATS (BT * LDIM + BT * H1D + BT * H2D)   // 57344
#define SMEM_BYTES  (SMEM_FLOATS * 4)                   // 229376

// round fp32 -> tf32 (rna), result bits in a b32 register
__device__ __forceinline__ uint32_t f2t(float f) {
    uint32_t u;
    asm("cvt.rna.tf32.f32 %0, %1;" : "=r"(u) : "f"(f));
    return u;
}

__device__ __forceinline__ void mma8(float c[4],
                                     uint32_t a0, uint32_t a1, uint32_t a2, uint32_t a3,
                                     uint32_t b0, uint32_t b1) {
    asm volatile(
        "mma.sync.aligned.m16n8k8.row.col.f32.tf32.tf32.f32 "
        "{%0,%1,%2,%3}, {%4,%5,%6,%7}, {%8,%9}, {%0,%1,%2,%3};"
        : "+f"(c[0]), "+f"(c[1]), "+f"(c[2]), "+f"(c[3])
        : "r"(a0), "r"(a1), "r"(a2), "r"(a3), "r"(b0), "r"(b1));
}

__device__ __forceinline__ float leaky(float v) {
    return v >= 0.f ? v : 0.01f * v;
}

// A-fragment loader from XOR-swizzled SMEM (row stride must be mult of 32).
// Fragment layout for m16n8k8 tf32 (thread t: g=t/4, tq=t%4):
//   a0=(g,   k), a1=(g+8, k), a2=(g, k+4), a3=(g+8, k+4)
__device__ __forceinline__ void lda(uint32_t a[4], const float* S, int stride,
                                    int r0, int tq, int k0) {
    const int sw = (r0 & 7) << 2;           // (r0+8)&7 == r0&7
    const int k  = k0 + tq;
    a[0] = __float_as_uint(S[r0 * stride       + (k ^ sw)]);
    a[1] = __float_as_uint(S[(r0 + 8) * stride + (k ^ sw)]);
    a[2] = __float_as_uint(S[r0 * stride       + ((k + 4) ^ sw)]);
    a[3] = __float_as_uint(S[(r0 + 8) * stride + ((k + 4) ^ sw)]);
}

__global__ void __launch_bounds__(NTHREADS, 1)
moe_fused_kernel(const float* __restrict__ x,
                 const float* __restrict__ W1, const float* __restrict__ b1,
                 const float* __restrict__ W2, const float* __restrict__ b2,
                 const float* __restrict__ W3, const float* __restrict__ b3,
                 const float* __restrict__ Wg, const float* __restrict__ bg,
                 float* __restrict__ out) {
    extern __shared__ float sm[];
    float* xs  = sm;                          // [BT][LDIM] swizzled tf32
    float* h1s = sm + BT * LDIM;              // [BT][H1D]  swizzled tf32
    float* h2s = sm + BT * LDIM + BT * H1D;   // [BT][H2D]  swizzled tf32

    const int tid  = threadIdx.x;
    const int w    = tid >> 5;
    const int lane = tid & 31;
    const int g    = lane >> 2;   // 0..7
    const int tq   = lane & 3;    // 0..3
    const int mw   = w & 7;       // m-tile (8 tiles of 16 rows)
    const int grp  = w >> 3;      // column group 0/1

    const int btile = blockIdx.x >> 1;
    const int octa  = (blockIdx.x & 1) * OC;  // 0 or 128
    const int row0  = btile * BT;
    const int ar    = mw * 16 + g;            // A-fragment base row in tile

    // ---- load x tile -> tf32 -> swizzled SMEM (float4, swizzle keeps 4-contig) ----
    for (int i = tid; i < BT * (LDIM / 4); i += NTHREADS) {
        const int r  = i >> 6;          // / (LDIM/4)
        const int c4 = i & 63;
        float4 v = reinterpret_cast<const float4*>(x + (size_t)(row0 + r) * LDIM)[c4];
        float4 t;
        t.x = __uint_as_float(f2t(v.x));
        t.y = __uint_as_float(f2t(v.y));
        t.z = __uint_as_float(f2t(v.z));
        t.w = __uint_as_float(f2t(v.w));
        const int col = c4 * 4;
        *reinterpret_cast<float4*>(xs + r * LDIM + (col ^ ((r & 7) << 2))) = t;
    }
    __syncthreads();

    // persistent gated accumulators for this warp's 64 output cols (8 n-tiles)
    float acc[8][4], ssum[8][4];
#pragma unroll
    for (int i = 0; i < 8; i++)
#pragma unroll
        for (int j = 0; j < 4; j++) { acc[i][j] = 0.f; ssum[i][j] = 0.f; }

    for (int e = 0; e < NE; e++) {
        // ================= layer 1: h1 = leaky(x @ W1_e + b1_e) ================
        {
            float c1[8][4];
#pragma unroll
            for (int i = 0; i < 8; i++)
#pragma unroll
                for (int j = 0; j < 4; j++) c1[i][j] = 0.f;

            const float* wp = W1 + e * (LDIM * H1D) + tq * H1D + grp * 64 + g;
#pragma unroll 2
            for (int k0 = 0; k0 < LDIM; k0 += 8) {
                uint32_t a[4];
                lda(a, xs, LDIM, ar, tq, k0);
                const float* p0 = wp + k0 * H1D;
                const float* p1 = p0 + 4 * H1D;
#pragma unroll
                for (int nt = 0; nt < 8; nt++) {
                    const uint32_t b0v = f2t(p0[nt * 8]);
                    const uint32_t b1v = f2t(p1[nt * 8]);
                    mma8(c1[nt], a[0], a[1], a[2], a[3], b0v, b1v);
                }
            }
            // bias + leaky + tf32 round -> h1s
            const int sw = (ar & 7) << 2;
#pragma unroll
            for (int nt = 0; nt < 8; nt++) {
                const int colb = grp * 64 + nt * 8 + 2 * tq;
                const float bb0 = b1[e * H1D + colb];
                const float bb1 = b1[e * H1D + colb + 1];
                float2 v0, v1;
                v0.x = __uint_as_float(f2t(leaky(c1[nt][0] + bb0)));
                v0.y = __uint_as_float(f2t(leaky(c1[nt][1] + bb1)));
                v1.x = __uint_as_float(f2t(leaky(c1[nt][2] + bb0)));
                v1.y = __uint_as_float(f2t(leaky(c1[nt][3] + bb1)));
                *reinterpret_cast<float2*>(h1s + ar * H1D + (colb ^ sw))       = v0;
                *reinterpret_cast<float2*>(h1s + (ar + 8) * H1D + (colb ^ sw)) = v1;
            }
        }
        __syncthreads();

        // ================= layer 2: h2 = leaky(h1 @ W2_e + b2_e) ===============
        {
            float c2[4][4];
#pragma unroll
            for (int i = 0; i < 4; i++)
#pragma unroll
                for (int j = 0; j < 4; j++) c2[i][j] = 0.f;

            const float* wp = W2 + e * (H1D * H2D) + tq * H2D + grp * 32 + g;
#pragma unroll 2
            for (int k0 = 0; k0 < H1D; k0 += 8) {
                uint32_t a[4];
                lda(a, h1s, H1D, ar, tq, k0);
                const float* p0 = wp + k0 * H2D;
                const float* p1 = p0 + 4 * H2D;
#pragma unroll
                for (int nt = 0; nt < 4; nt++) {
                    const uint32_t b0v = f2t(p0[nt * 8]);
                    const uint32_t b1v = f2t(p1[nt * 8]);
                    mma8(c2[nt], a[0], a[1], a[2], a[3], b0v, b1v);
                }
            }
            const int sw = (ar & 7) << 2;
#pragma unroll
            for (int nt = 0; nt < 4; nt++) {
                const int colb = grp * 32 + nt * 8 + 2 * tq;
                const float bb0 = b2[e * H2D + colb];
                const float bb1 = b2[e * H2D + colb + 1];
                float2 v0, v1;
                v0.x = __uint_as_float(f2t(leaky(c2[nt][0] + bb0)));
                v0.y = __uint_as_float(f2t(leaky(c2[nt][1] + bb1)));
                v1.x = __uint_as_float(f2t(leaky(c2[nt][2] + bb0)));
                v1.y = __uint_as_float(f2t(leaky(c2[nt][3] + bb1)));
                *reinterpret_cast<float2*>(h2s + ar * H2D + (colb ^ sw))       = v0;
                *reinterpret_cast<float2*>(h2s + (ar + 8) * H2D + (colb ^ sw)) = v1;
            }
        }
        __syncthreads();

        // ====== gate + layer 3 + online gated accumulation (per 32-col sub) ====
#pragma unroll 1
        for (int os = 0; os < 2; os++) {
            float cg[4][4], co[4][4];
#pragma unroll
            for (int i = 0; i < 4; i++)
#pragma unroll
                for (int j = 0; j < 4; j++) { cg[i][j] = 0.f; co[i][j] = 0.f; }

            const int nbase = octa + grp * 64 + os * 32 + g;  // global out col of b-frag

            // gate GEMM: xs[BT,L] @ Wg[:, e*O + nbase...]
            const float* wg0 = Wg + e * ODIM + nbase + tq * EO;
#pragma unroll 2
            for (int k0 = 0; k0 < LDIM; k0 += 8) {
                uint32_t a[4];
                lda(a, xs, LDIM, ar, tq, k0);
                const float* p0 = wg0 + k0 * EO;
                const float* p1 = p0 + 4 * EO;
#pragma unroll
                for (int nt = 0; nt < 4; nt++) {
                    const uint32_t b0v = f2t(p0[nt * 8]);
                    const uint32_t b1v = f2t(p1[nt * 8]);
                    mma8(cg[nt], a[0], a[1], a[2], a[3], b0v, b1v);
                }
            }
            // layer3 GEMM: h2s[BT,H2] @ W3_e[:, nbase...]
            const float* w30 = W3 + e * (H2D * ODIM) + nbase + tq * ODIM;
#pragma unroll
            for (int k0 = 0; k0 < H2D; k0 += 8) {
                uint32_t a[4];
                lda(a, h2s, H2D, ar, tq, k0);
                const float* p0 = w30 + k0 * ODIM;
                const float* p1 = p0 + 4 * ODIM;
#pragma unroll
                for (int nt = 0; nt < 4; nt++) {
                    const uint32_t b0v = f2t(p0[nt * 8]);
                    const uint32_t b1v = f2t(p1[nt * 8]);
                    mma8(co[nt], a[0], a[1], a[2], a[3], b0v, b1v);
                }
            }
            // fold: acc += exp(g+bg)*(o+b3); s += exp(g+bg)
#pragma unroll
            for (int nt = 0; nt < 4; nt++) {
                const int colc = octa + grp * 64 + os * 32 + nt * 8 + 2 * tq;
                const float bg0 = bg[e * ODIM + colc];
                const float bg1 = bg[e * ODIM + colc + 1];
                const float b30 = b3[e * ODIM + colc];
                const float b31 = b3[e * ODIM + colc + 1];
                const int ai = os * 4 + nt;
                float p;
                p = __expf(cg[nt][0] + bg0); acc[ai][0] += p * (co[nt][0] + b30); ssum[ai][0] += p;
                p = __expf(cg[nt][1] + bg1); acc[ai][1] += p * (co[nt][1] + b31); ssum[ai][1] += p;
                p = __expf(cg[nt][2] + bg0); acc[ai][2] += p * (co[nt][2] + b30); ssum[ai][2] += p;
                p = __expf(cg[nt][3] + bg1); acc[ai][3] += p * (co[nt][3] + b31); ssum[ai][3] += p;
            }
        }
        // no sync needed here: next expert's first hazard (h2s write in layer 2)
        // is fenced by the __syncthreads after its layer-1 epilogue.
    }

    // ---- epilogue: out = acc / ssum ----
#pragma unroll
    for (int ai = 0; ai < 8; ai++) {
        const int os = ai >> 2, nt = ai & 3;
        const int colc = octa + grp * 64 + os * 32 + nt * 8 + 2 * tq;
        const size_t r0 = (size_t)(row0 + ar) * ODIM;
        const size_t r1 = (size_t)(row0 + ar + 8) * ODIM;
        float2 v0 = make_float2(acc[ai][0] / ssum[ai][0], acc[ai][1] / ssum[ai][1]);
        float2 v1 = make_float2(acc[ai][2] / ssum[ai][2], acc[ai][3] / ssum[ai][3]);
        *reinterpret_cast<float2*>(out + r0 + colc) = v0;
        *reinterpret_cast<float2*>(out + r1 + colc) = v1;
    }
}

extern "C" void kernel_launch(void* const* d_in, const int* in_sizes, int n_in,
                              void* d_out, int out_size) {
    const float* x  = (const float*)d_in[0];
    const float* W1 = (const float*)d_in[1];
    const float* b1 = (const float*)d_in[2];
    const float* W2 = (const float*)d_in[3];
    const float* b2 = (const float*)d_in[4];
    const float* W3 = (const float*)d_in[5];
    const float* b3 = (const float*)d_in[6];
    const float* Wg = (const float*)d_in[7];
    const float* bg = (const float*)d_in[8];
    float* out = (float*)d_out;

    (void)n_in; (void)out_size;
    const int B  = in_sizes[0] / LDIM;      // 65536
    const int nb = (B / BT) * (ODIM / OC);  // 1024 CTAs

    cudaFuncSetAttribute(moe_fused_kernel,
                         cudaFuncAttributeMaxDynamicSharedMemorySize, SMEM_BYTES);
    moe_fused_kernel<<<nb, NTHREADS, SMEM_BYTES>>>(x, W1, b1, W2, b2, W3, b3, Wg, bg, out);
}

// round 3
// speedup vs baseline: 1.9990x; 1.9990x over previous
#include <cuda_runtime.h>
#include <cstdint>
#include <cstddef>

// ---------------------------------------------------------------------------
// Fused MoE element-wise gating, round 2 (resubmit after infra failure):
// SMEM-staged weights + ldmatrix.
// out[b,o] = sum_e softmax_e(x@Wg+bg) * (L3(L2(L1(x)))+b3)
// B=65536, L=256, E=8, H1=128, H2=64, O=256, fp32 (tf32 mma, fp32 accum).
//
// CTA: 128 rows x 128 out-cols. 512 thr = 16 warps = 8 m-tiles x 2 col-grps.
// All mma operands from SMEM: A via ldmatrix.x4, B via conflict-free swizzled
// LDS.32 from cp.async-staged weight tiles aliased into dead h1/h2 regions.
// Weights pre-rounded to tf32 once per launch into __device__ scratch.
// ---------------------------------------------------------------------------

#define BT 128
#define LDIM 256
#define ODIM 256
#define NE 8
#define H1D 128
#define H2D 64
#define EO 2048
#define OC 128
#define NTHREADS 512

// SMEM map (float words)
#define XS_OFF 0            // x tile   [128][256] swizzled         (128 KB)
#define H1_OFF 32768        // h1 tile  [128][128] / W3+Wg staging  ( 64 KB)
#define H2_OFF 49152        // h2 tile  [128][64]  / W1,W2 staging  ( 32 KB)
#define SMEM_WORDS 57344
#define SMEM_BYTES (SMEM_WORDS * 4)

#define W1BUF(i) (H2_OFF + (i) * 4096)   // 2 x [32][128] chunks
#define W2BUF    H2_OFF                  // [128][64] full
#define W3BUF    (H1_OFF + 8192)         // [64][128] full
#define WGBUF(i) (H1_OFF + (i) * 4096)   // 2 x [32][128] chunks

// tf32-rounded weight scratch in device global memory (~3.93 MB)
#define W1S_OFF 0
#define W2S_OFF 262144
#define W3S_OFF 327680
#define WGS_OFF 458752
#define WS_TOTAL 983040
__device__ float g_ws[WS_TOTAL];

__device__ __forceinline__ uint32_t f2t(float f) {
    uint32_t u;
    asm("cvt.rna.tf32.f32 %0, %1;" : "=r"(u) : "f"(f));
    return u;
}

__device__ __forceinline__ void mma8(float c[4],
                                     uint32_t a0, uint32_t a1, uint32_t a2, uint32_t a3,
                                     uint32_t b0, uint32_t b1) {
    asm volatile(
        "mma.sync.aligned.m16n8k8.row.col.f32.tf32.tf32.f32 "
        "{%0,%1,%2,%3}, {%4,%5,%6,%7}, {%8,%9}, {%0,%1,%2,%3};"
        : "+f"(c[0]), "+f"(c[1]), "+f"(c[2]), "+f"(c[3])
        : "r"(a0), "r"(a1), "r"(a2), "r"(a3), "r"(b0), "r"(b1));
}

__device__ __forceinline__ float leaky(float v) { return v >= 0.f ? v : 0.01f * v; }

__device__ __forceinline__ void ldsm4(uint32_t a[4], uint32_t addr) {
    asm volatile("ldmatrix.sync.aligned.m8n8.x4.shared.b16 {%0,%1,%2,%3}, [%4];"
                 : "=r"(a[0]), "=r"(a[1]), "=r"(a[2]), "=r"(a[3])
                 : "r"(addr));
}

__device__ __forceinline__ void cpa16(uint32_t saddr, const float* g) {
    asm volatile("cp.async.cg.shared.global [%0], [%1], 16;" :: "r"(saddr), "l"(g));
}
#define CP_COMMIT() asm volatile("cp.async.commit_group;" ::: "memory")
#define CP_WAIT0()  asm volatile("cp.async.wait_group 0;" ::: "memory")

// Cooperative tile stage: global [R rows x W cols] -> SMEM, B-swizzle
// (col ^ ((row&3)<<3)) which keeps 16B granules contiguous and makes the
// per-mma B LDS.32 (4 k-rows x 8 n) bank-conflict-free.
template<int R, int W>
__device__ __forceinline__ void stage_tile(uint32_t sb, int dstWord, const float* g,
                                           int gstride, int tid) {
    constexpr int GR = W / 4;
    constexpr int TOT = R * GR;
#pragma unroll
    for (int i = 0; i < TOT; i += NTHREADS) {
        const int idx = i + tid;
        const int r = idx / GR;
        const int n0 = (idx - r * GR) << 2;
        cpa16(sb + ((dstWord + r * W + (n0 ^ ((r & 3) << 3))) << 2),
              g + (size_t)r * gstride + n0);
    }
}

// pre-round all weights to tf32 (RNA) once per launch
__global__ void prep_weights(const float* __restrict__ W1, const float* __restrict__ W2,
                             const float* __restrict__ W3, const float* __restrict__ Wg) {
    const int stride = gridDim.x * blockDim.x;
    const int i0 = blockIdx.x * blockDim.x + threadIdx.x;
    for (int i = i0; i < 262144; i += stride) g_ws[W1S_OFF + i] = __uint_as_float(f2t(W1[i]));
    for (int i = i0; i < 65536;  i += stride) g_ws[W2S_OFF + i] = __uint_as_float(f2t(W2[i]));
    for (int i = i0; i < 131072; i += stride) g_ws[W3S_OFF + i] = __uint_as_float(f2t(W3[i]));
    for (int i = i0; i < 524288; i += stride) g_ws[WGS_OFF + i] = __uint_as_float(f2t(Wg[i]));
}

__global__ void __launch_bounds__(NTHREADS, 1)
moe_fused_kernel(const float* __restrict__ x,
                 const float* __restrict__ b1, const float* __restrict__ b2,
                 const float* __restrict__ b3, const float* __restrict__ bg,
                 float* __restrict__ out) {
    extern __shared__ float sm[];
    const uint32_t sb = (uint32_t)__cvta_generic_to_shared(sm);

    const int tid  = threadIdx.x;
    const int w    = tid >> 5;
    const int lane = tid & 31;
    const int g    = lane >> 2;
    const int tq   = lane & 3;
    const int mw   = w & 7;        // m-tile (16 rows)
    const int grp  = w >> 3;       // 64-col group

    const int btile = blockIdx.x >> 1;
    const int octa  = (blockIdx.x & 1) * OC;
    const int row0  = btile * BT;
    const int ar    = mw * 16 + g;             // D/A fragment base row

    // ldmatrix per-lane constants
    const int lrow = (mw << 4) + (((lane >> 3) & 1) << 3) + (lane & 7);
    const int lsw  = (lrow & 7) << 2;
    const int lcb  = (lane >> 4) << 2;
    const uint32_t xsRow = sb + (uint32_t)((XS_OFF + lrow * LDIM) << 2);
    const uint32_t h1Row = sb + (uint32_t)((H1_OFF + lrow * H1D) << 2);
    const uint32_t h2Row = sb + (uint32_t)((H2_OFF + lrow * H2D) << 2);

    // ---- load x tile -> tf32 -> swizzled SMEM ----
    for (int i = tid; i < BT * (LDIM / 4); i += NTHREADS) {
        const int r  = i >> 6;
        const int c4 = i & 63;
        float4 v = reinterpret_cast<const float4*>(x + (size_t)(row0 + r) * LDIM)[c4];
        float4 t;
        t.x = __uint_as_float(f2t(v.x));
        t.y = __uint_as_float(f2t(v.y));
        t.z = __uint_as_float(f2t(v.z));
        t.w = __uint_as_float(f2t(v.w));
        const int col = c4 * 4;
        *reinterpret_cast<float4*>(sm + XS_OFF + r * LDIM + (col ^ ((r & 7) << 2))) = t;
    }

    float acc[8][4], ssum[8][4];
#pragma unroll
    for (int i = 0; i < 8; i++)
#pragma unroll
        for (int j = 0; j < 4; j++) { acc[i][j] = 0.f; ssum[i][j] = 0.f; }

    const float* W1s = g_ws + W1S_OFF;
    const float* W2s = g_ws + W2S_OFF;
    const float* W3s = g_ws + W3S_OFF;
    const float* Wgs = g_ws + WGS_OFF;

    for (int e = 0; e < NE; e++) {
        __syncthreads();   // S0: h2/h1 staging regions free (prev expert done; or xs ready)

        // ================= layer 1: h1 = leaky(x @ W1_e + b1_e) ================
        stage_tile<32, 128>(sb, W1BUF(0), W1s + e * 32768, H1D, tid);
        CP_COMMIT();

        float c1[8][4];
#pragma unroll
        for (int i = 0; i < 8; i++)
#pragma unroll
            for (int j = 0; j < 4; j++) c1[i][j] = 0.f;

        const int nb1 = grp * 64 + g;
        for (int c = 0; c < 8; c++) {
            CP_WAIT0();
            __syncthreads();
            if (c < 7) {
                stage_tile<32, 128>(sb, W1BUF((c + 1) & 1),
                                    W1s + e * 32768 + ((c + 1) << 5) * H1D, H1D, tid);
                CP_COMMIT();
            }
            const uint32_t* wb = reinterpret_cast<const uint32_t*>(sm + W1BUF(c & 1));
#pragma unroll
            for (int ks = 0; ks < 4; ks++) {
                uint32_t a[4];
                ldsm4(a, xsRow + (uint32_t)((((c << 5) + (ks << 3) + lcb) ^ lsw) << 2));
                const int r0 = ((ks << 3) + tq) * H1D;
                const int r1 = r0 + 4 * H1D;
#pragma unroll
                for (int nt = 0; nt < 8; nt++) {
                    const int cs = nb1 + ((nt ^ tq) << 3);
                    mma8(c1[nt], a[0], a[1], a[2], a[3], wb[r0 + cs], wb[r1 + cs]);
                }
            }
        }
        // h1 epilogue
        {
            const int sw = (ar & 7) << 2;
#pragma unroll
            for (int nt = 0; nt < 8; nt++) {
                const int colb = grp * 64 + nt * 8 + 2 * tq;
                const float bb0 = b1[e * H1D + colb];
                const float bb1 = b1[e * H1D + colb + 1];
                float2 v0, v1;
                v0.x = __uint_as_float(f2t(leaky(c1[nt][0] + bb0)));
                v0.y = __uint_as_float(f2t(leaky(c1[nt][1] + bb1)));
                v1.x = __uint_as_float(f2t(leaky(c1[nt][2] + bb0)));
                v1.y = __uint_as_float(f2t(leaky(c1[nt][3] + bb1)));
                *reinterpret_cast<float2*>(sm + H1_OFF + ar * H1D + (colb ^ sw))       = v0;
                *reinterpret_cast<float2*>(sm + H1_OFF + (ar + 8) * H1D + (colb ^ sw)) = v1;
            }
        }
        __syncthreads();   // h1 visible; W1 bufs free

        // ================= layer 2: h2 = leaky(h1 @ W2_e + b2_e) ===============
        stage_tile<128, 64>(sb, W2BUF, W2s + e * 8192, H2D, tid);
        CP_COMMIT();
        CP_WAIT0();
        __syncthreads();   // W2 visible

        float c2[4][4];
#pragma unroll
        for (int i = 0; i < 4; i++)
#pragma unroll
            for (int j = 0; j < 4; j++) c2[i][j] = 0.f;

        const int nb2 = grp * 32 + g;
        {
            const uint32_t* wb = reinterpret_cast<const uint32_t*>(sm + W2BUF);
#pragma unroll
            for (int ks = 0; ks < 16; ks++) {
                uint32_t a[4];
                ldsm4(a, h1Row + (uint32_t)((((ks << 3) + lcb) ^ lsw) << 2));
                const int r0 = ((ks << 3) + tq) * H2D;
                const int r1 = r0 + 4 * H2D;
#pragma unroll
                for (int nt = 0; nt < 4; nt++) {
                    const int cs = nb2 + ((nt ^ tq) << 3);
                    mma8(c2[nt], a[0], a[1], a[2], a[3], wb[r0 + cs], wb[r1 + cs]);
                }
            }
        }
        __syncthreads();   // all done reading W2 + h1

        // h2 epilogue (overwrites W2 staging region)
        {
            const int sw = (ar & 7) << 2;
#pragma unroll
            for (int nt = 0; nt < 4; nt++) {
                const int colb = grp * 32 + nt * 8 + 2 * tq;
                const float bb0 = b2[e * H2D + colb];
                const float bb1 = b2[e * H2D + colb + 1];
                float2 v0, v1;
                v0.x = __uint_as_float(f2t(leaky(c2[nt][0] + bb0)));
                v0.y = __uint_as_float(f2t(leaky(c2[nt][1] + bb1)));
                v1.x = __uint_as_float(f2t(leaky(c2[nt][2] + bb0)));
                v1.y = __uint_as_float(f2t(leaky(c2[nt][3] + bb1)));
                *reinterpret_cast<float2*>(sm + H2_OFF + ar * H2D + (colb ^ sw))       = v0;
                *reinterpret_cast<float2*>(sm + H2_OFF + (ar + 8) * H2D + (colb ^ sw)) = v1;
            }
        }

        // stage W3 (full) + first Wg chunk into h1 region (h1 dead now)
        stage_tile<64, 128>(sb, W3BUF, W3s + e * 16384 + octa, ODIM, tid);
        CP_COMMIT();

        // ====== gate GEMM (os-inner, shared A) =================================
        float cg[2][4][4];
#pragma unroll
        for (int o = 0; o < 2; o++)
#pragma unroll
            for (int i = 0; i < 4; i++)
#pragma unroll
                for (int j = 0; j < 4; j++) cg[o][i][j] = 0.f;

        stage_tile<32, 128>(sb, WGBUF(0), Wgs + e * ODIM + octa, EO, tid);
        CP_COMMIT();

        const int nbg = grp * 64 + g;
        for (int c = 0; c < 8; c++) {
            CP_WAIT0();        // waits chunk c (and W3 at c==0)
            __syncthreads();   // chunk visible; h2 writes visible (c==0)
            if (c < 7) {
                stage_tile<32, 128>(sb, WGBUF((c + 1) & 1),
                                    Wgs + ((c + 1) << 5) * EO + e * ODIM + octa, EO, tid);
                CP_COMMIT();
            }
            const uint32_t* wb = reinterpret_cast<const uint32_t*>(sm + WGBUF(c & 1));
#pragma unroll
            for (int ks = 0; ks < 4; ks++) {
                uint32_t a[4];
                ldsm4(a, xsRow + (uint32_t)((((c << 5) + (ks << 3) + lcb) ^ lsw) << 2));
                const int r0 = ((ks << 3) + tq) * OC;
                const int r1 = r0 + 4 * OC;
#pragma unroll
                for (int os = 0; os < 2; os++)
#pragma unroll
                    for (int nt = 0; nt < 4; nt++) {
                        const int cs = nbg + (os << 5) + ((nt ^ tq) << 3);
                        mma8(cg[os][nt], a[0], a[1], a[2], a[3], wb[r0 + cs], wb[r1 + cs]);
                    }
            }
        }

        // ====== layer 3 + fold, per 32-col half ===============================
        const uint32_t* w3 = reinterpret_cast<const uint32_t*>(sm + W3BUF);
#pragma unroll 1
        for (int os = 0; os < 2; os++) {
            float co[4][4];
#pragma unroll
            for (int i = 0; i < 4; i++)
#pragma unroll
                for (int j = 0; j < 4; j++) co[i][j] = 0.f;

#pragma unroll
            for (int ks = 0; ks < 8; ks++) {
                uint32_t a[4];
                ldsm4(a, h2Row + (uint32_t)((((ks << 3) + lcb) ^ lsw) << 2));
                const int r0 = ((ks << 3) + tq) * OC;
                const int r1 = r0 + 4 * OC;
#pragma unroll
                for (int nt = 0; nt < 4; nt++) {
                    const int cs = nbg + (os << 5) + ((nt ^ tq) << 3);
                    mma8(co[nt], a[0], a[1], a[2], a[3], w3[r0 + cs], w3[r1 + cs]);
                }
            }
#pragma unroll
            for (int nt = 0; nt < 4; nt++) {
                const int colc = octa + grp * 64 + os * 32 + nt * 8 + 2 * tq;
                const float bg0 = bg[e * ODIM + colc];
                const float bg1 = bg[e * ODIM + colc + 1];
                const float b30 = b3[e * ODIM + colc];
                const float b31 = b3[e * ODIM + colc + 1];
                const int ai = os * 4 + nt;
                float p;
                p = __expf(cg[os][nt][0] + bg0); acc[ai][0] += p * (co[nt][0] + b30); ssum[ai][0] += p;
                p = __expf(cg[os][nt][1] + bg1); acc[ai][1] += p * (co[nt][1] + b31); ssum[ai][1] += p;
                p = __expf(cg[os][nt][2] + bg0); acc[ai][2] += p * (co[nt][2] + b30); ssum[ai][2] += p;
                p = __expf(cg[os][nt][3] + bg1); acc[ai][3] += p * (co[nt][3] + b31); ssum[ai][3] += p;
            }
        }
        // expert-top S0 guards h2/W3/Wg reuse
    }

    // ---- epilogue: out = acc / ssum ----
#pragma unroll
    for (int ai = 0; ai < 8; ai++) {
        const int os = ai >> 2, nt = ai & 3;
        const int colc = octa + grp * 64 + os * 32 + nt * 8 + 2 * tq;
        const size_t r0 = (size_t)(row0 + ar) * ODIM;
        const size_t r1 = (size_t)(row0 + ar + 8) * ODIM;
        float2 v0 = make_float2(acc[ai][0] / ssum[ai][0], acc[ai][1] / ssum[ai][1]);
        float2 v1 = make_float2(acc[ai][2] / ssum[ai][2], acc[ai][3] / ssum[ai][3]);
        *reinterpret_cast<float2*>(out + r0 + colc) = v0;
        *reinterpret_cast<float2*>(out + r1 + colc) = v1;
    }
}

extern "C" void kernel_launch(void* const* d_in, const int* in_sizes, int n_in,
                              void* d_out, int out_size) {
    const float* x  = (const float*)d_in[0];
    const float* W1 = (const float*)d_in[1];
    const float* b1 = (const float*)d_in[2];
    const float* W2 = (const float*)d_in[3];
    const float* b2 = (const float*)d_in[4];
    const float* W3 = (const float*)d_in[5];
    const float* b3 = (const float*)d_in[6];
    const float* Wg = (const float*)d_in[7];
    const float* bg = (const float*)d_in[8];
    float* out = (float*)d_out;

    (void)n_in; (void)out_size;
    const int B  = in_sizes[0] / LDIM;       // 65536
    const int nb = (B / BT) * (ODIM / OC);   // 1024 CTAs

    prep_weights<<<512, 256>>>(W1, W2, W3, Wg);

    cudaFuncSetAttribute(moe_fused_kernel,
                         cudaFuncAttributeMaxDynamicSharedMemorySize, SMEM_BYTES);
    moe_fused_kernel<<<nb, NTHREADS, SMEM_BYTES>>>(x, b1, b2, b3, bg, out);
}

// round 8
// speedup vs baseline: 2.0499x; 1.0255x over previous
#include <cuda_runtime.h>
#include <cstdint>
#include <cstddef>

// ---------------------------------------------------------------------------
// Fused MoE element-wise gating, round 8: round-3 core + m32n32 warp blocking
// (ONE isolated change; B fragments reused across 2 m-tiles).
// out[b,o] = sum_e softmax_e(x@Wg+bg) * (L3(L2(L1(x)))+b3)
// B=65536, L=256, E=8, H1=128, H2=64, O=256, fp32 (tf32 mma, fp32 accum).
//
// CTA: 128 rows x 128 out-cols, 512 thr = 16 warps = 4 m-warps x 4 n-groups.
// B staged via round-3 stage_tile (granule swizzle n0 ^ ((r&3)<<3)), consumed
// with the general XOR form (n ^ (tq<<3)). A via ldmatrix.x4 (two per slice).
// ---------------------------------------------------------------------------

#define BT 128
#define LDIM 256
#define ODIM 256
#define NE 8
#define H1D 128
#define H2D 64
#define EO 2048
#define OC 128
#define NTHREADS 512

// SMEM map (float words)
#define XS_OFF 0            // x tile   [128][256] swizzled         (128 KB)
#define H1_OFF 32768        // h1 tile  [128][128] / W3+Wg staging  ( 64 KB)
#define H2_OFF 49152        // h2 tile  [128][64]  / W1,W2 staging  ( 32 KB)
#define SMEM_WORDS 57344
#define SMEM_BYTES (SMEM_WORDS * 4)

#define W1BUF(i) (H2_OFF + (i) * 4096)   // 2 x [32][128] chunks
#define W2BUF    H2_OFF                  // [128][64] full
#define W3BUF    (H1_OFF + 8192)         // [64][128] full
#define WGBUF(i) (H1_OFF + (i) * 4096)   // 2 x [32][128] chunks

// tf32-rounded weight scratch in device global memory (~3.93 MB)
#define W1S_OFF 0
#define W2S_OFF 262144
#define W3S_OFF 327680
#define WGS_OFF 458752
#define WS_TOTAL 983040
__device__ float g_ws[WS_TOTAL];

__device__ __forceinline__ uint32_t f2t(float f) {
    uint32_t u;
    asm("cvt.rna.tf32.f32 %0, %1;" : "=r"(u) : "f"(f));
    return u;
}

__device__ __forceinline__ void mma8(float c[4],
                                     uint32_t a0, uint32_t a1, uint32_t a2, uint32_t a3,
                                     uint32_t b0, uint32_t b1) {
    asm volatile(
        "mma.sync.aligned.m16n8k8.row.col.f32.tf32.tf32.f32 "
        "{%0,%1,%2,%3}, {%4,%5,%6,%7}, {%8,%9}, {%0,%1,%2,%3};"
        : "+f"(c[0]), "+f"(c[1]), "+f"(c[2]), "+f"(c[3])
        : "r"(a0), "r"(a1), "r"(a2), "r"(a3), "r"(b0), "r"(b1));
}

__device__ __forceinline__ float leaky(float v) { return v >= 0.f ? v : 0.01f * v; }

__device__ __forceinline__ void ldsm4(uint32_t a[4], uint32_t addr) {
    asm volatile("ldmatrix.sync.aligned.m8n8.x4.shared.b16 {%0,%1,%2,%3}, [%4];"
                 : "=r"(a[0]), "=r"(a[1]), "=r"(a[2]), "=r"(a[3])
                 : "r"(addr));
}

__device__ __forceinline__ void cpa16(uint32_t saddr, const float* g) {
    asm volatile("cp.async.cg.shared.global [%0], [%1], 16;" :: "r"(saddr), "l"(g));
}
#define CP_COMMIT() asm volatile("cp.async.commit_group;" ::: "memory")
#define CP_WAIT0()  asm volatile("cp.async.wait_group 0;" ::: "memory")

// Cooperative tile stage: global [R rows x W cols] -> SMEM, B-swizzle
// (n0 ^ ((r&3)<<3)); consumer uses word = r*W + (n ^ (tq<<3)).
template<int R, int W>
__device__ __forceinline__ void stage_tile(uint32_t sb, int dstWord, const float* g,
                                           int gstride, int tid) {
    constexpr int GR = W / 4;
    constexpr int TOT = R * GR;
#pragma unroll
    for (int i = 0; i < TOT; i += NTHREADS) {
        const int idx = i + tid;
        const int r = idx / GR;
        const int n0 = (idx - r * GR) << 2;
        cpa16(sb + ((dstWord + r * W + (n0 ^ ((r & 3) << 3))) << 2),
              g + (size_t)r * gstride + n0);
    }
}

// pre-round all weights to tf32 (RNA) once per launch
__global__ void prep_weights(const float* __restrict__ W1, const float* __restrict__ W2,
                             const float* __restrict__ W3, const float* __restrict__ Wg) {
    const int stride = gridDim.x * blockDim.x;
    const int i0 = blockIdx.x * blockDim.x + threadIdx.x;
    for (int i = i0; i < 262144; i += stride) g_ws[W1S_OFF + i] = __uint_as_float(f2t(W1[i]));
    for (int i = i0; i < 65536;  i += stride) g_ws[W2S_OFF + i] = __uint_as_float(f2t(W2[i]));
    for (int i = i0; i < 131072; i += stride) g_ws[W3S_OFF + i] = __uint_as_float(f2t(W3[i]));
    for (int i = i0; i < 524288; i += stride) g_ws[WGS_OFF + i] = __uint_as_float(f2t(Wg[i]));
}

__global__ void __launch_bounds__(NTHREADS, 1)
moe_fused_kernel(const float* __restrict__ x,
                 const float* __restrict__ b1, const float* __restrict__ b2,
                 const float* __restrict__ b3, const float* __restrict__ bg,
                 float* __restrict__ out) {
    extern __shared__ float sm[];
    const uint32_t sb = (uint32_t)__cvta_generic_to_shared(sm);

    const int tid  = threadIdx.x;
    const int w    = tid >> 5;
    const int lane = tid & 31;
    const int g    = lane >> 2;    // 0..7
    const int tq   = lane & 3;     // 0..3
    const int mq   = w & 3;        // m-warp: rows mq*32 .. +31 (2 m16 tiles)
    const int ng   = w >> 2;       // n-group: 32 cols

    const int btile = blockIdx.x >> 1;
    const int octa  = (blockIdx.x & 1) * OC;
    const int row0  = btile * BT;

    // ldmatrix per-lane addressing; tile0 rows = mq*32+lbase, tile1 = +16
    const int lbase = (((lane >> 3) & 1) << 3) + (lane & 7);
    const int lrow0 = mq * 32 + lbase;
    const int lrow1 = lrow0 + 16;               // same low 3 bits
    const int lsw   = (lrow0 & 7) << 2;
    const int lcb   = (lane >> 4) << 2;
    const uint32_t xsRow0 = sb + (uint32_t)((XS_OFF + lrow0 * LDIM) << 2);
    const uint32_t xsRow1 = sb + (uint32_t)((XS_OFF + lrow1 * LDIM) << 2);
    const uint32_t h1Row0 = sb + (uint32_t)((H1_OFF + lrow0 * H1D) << 2);
    const uint32_t h1Row1 = sb + (uint32_t)((H1_OFF + lrow1 * H1D) << 2);
    const uint32_t h2Row0 = sb + (uint32_t)((H2_OFF + lrow0 * H2D) << 2);
    const uint32_t h2Row1 = sb + (uint32_t)((H2_OFF + lrow1 * H2D) << 2);

    const int nb1 = ng * 32 + g;   // N=128 GEMMs (L1, gate, L3)
    const int nb2 = ng * 16 + g;   // N=64 (L2)
    const int tqx = tq << 3;       // granule swizzle XOR

    // ---- load x tile -> tf32 -> swizzled SMEM ----
    for (int i = tid; i < BT * (LDIM / 4); i += NTHREADS) {
        const int r  = i >> 6;
        const int c4 = i & 63;
        float4 v = reinterpret_cast<const float4*>(x + (size_t)(row0 + r) * LDIM)[c4];
        v.x = __uint_as_float(f2t(v.x)); v.y = __uint_as_float(f2t(v.y));
        v.z = __uint_as_float(f2t(v.z)); v.w = __uint_as_float(f2t(v.w));
        const int col = c4 * 4;
        *reinterpret_cast<float4*>(sm + XS_OFF + r * LDIM + (col ^ ((r & 7) << 2))) = v;
    }

    float acc[8][4], ssum[8][4];
#pragma unroll
    for (int i = 0; i < 8; i++)
#pragma unroll
        for (int jj = 0; jj < 4; jj++) { acc[i][jj] = 0.f; ssum[i][jj] = 0.f; }

    const float* W1s = g_ws + W1S_OFF;
    const float* W2s = g_ws + W2S_OFF;
    const float* W3s = g_ws + W3S_OFF;
    const float* Wgs = g_ws + WGS_OFF;

    for (int e = 0; e < NE; e++) {
        __syncthreads();   // S0: h1/h2 staging regions free

        // ================= layer 1: h1 = leaky(x @ W1_e + b1_e) ================
        stage_tile<32, 128>(sb, W1BUF(0), W1s + e * 32768, H1D, tid);
        CP_COMMIT();

        float c1[2][4][4];
#pragma unroll
        for (int t = 0; t < 2; t++)
#pragma unroll
            for (int i = 0; i < 4; i++)
#pragma unroll
                for (int jj = 0; jj < 4; jj++) c1[t][i][jj] = 0.f;

        for (int c = 0; c < 8; c++) {
            CP_WAIT0();
            __syncthreads();
            if (c < 7) {
                stage_tile<32, 128>(sb, W1BUF((c + 1) & 1),
                                    W1s + e * 32768 + ((c + 1) << 5) * H1D, H1D, tid);
                CP_COMMIT();
            }
            const uint32_t* wb = reinterpret_cast<const uint32_t*>(sm + W1BUF(c & 1));
#pragma unroll
            for (int ks = 0; ks < 4; ks++) {
                const int kk = (c << 5) + (ks << 3) + lcb;
                uint32_t a0[4], a1[4];
                ldsm4(a0, xsRow0 + (uint32_t)((kk ^ lsw) << 2));
                ldsm4(a1, xsRow1 + (uint32_t)((kk ^ lsw) << 2));
                const int r0 = ((ks << 3) + tq) * H1D;
                const int r1 = r0 + 4 * H1D;
#pragma unroll
                for (int nt = 0; nt < 4; nt++) {
                    const int cs = (nb1 + (nt << 3)) ^ tqx;
                    const uint32_t b0v = wb[r0 + cs];
                    const uint32_t b1v = wb[r1 + cs];
                    mma8(c1[0][nt], a0[0], a0[1], a0[2], a0[3], b0v, b1v);
                    mma8(c1[1][nt], a1[0], a1[1], a1[2], a1[3], b0v, b1v);
                }
            }
        }
        // h1 epilogue
        {
#pragma unroll
            for (int t = 0; t < 2; t++) {
                const int ar = mq * 32 + t * 16 + g;
                const int sw = (ar & 7) << 2;     // == g<<2
#pragma unroll
                for (int nt = 0; nt < 4; nt++) {
                    const int colb = ng * 32 + nt * 8 + 2 * tq;
                    const float bb0 = b1[e * H1D + colb];
                    const float bb1 = b1[e * H1D + colb + 1];
                    float2 v0, v1;
                    v0.x = __uint_as_float(f2t(leaky(c1[t][nt][0] + bb0)));
                    v0.y = __uint_as_float(f2t(leaky(c1[t][nt][1] + bb1)));
                    v1.x = __uint_as_float(f2t(leaky(c1[t][nt][2] + bb0)));
                    v1.y = __uint_as_float(f2t(leaky(c1[t][nt][3] + bb1)));
                    *reinterpret_cast<float2*>(sm + H1_OFF + ar * H1D + (colb ^ sw))       = v0;
                    *reinterpret_cast<float2*>(sm + H1_OFF + (ar + 8) * H1D + (colb ^ sw)) = v1;
                }
            }
        }
        __syncthreads();   // h1 visible; W1 bufs free

        // ================= layer 2: h2 = leaky(h1 @ W2_e + b2_e) ===============
        stage_tile<128, 64>(sb, W2BUF, W2s + e * 8192, H2D, tid);
        CP_COMMIT();
        CP_WAIT0();
        __syncthreads();   // W2 visible

        float c2[2][2][4];
#pragma unroll
        for (int t = 0; t < 2; t++)
#pragma unroll
            for (int i = 0; i < 2; i++)
#pragma unroll
                for (int jj = 0; jj < 4; jj++) c2[t][i][jj] = 0.f;

        {
            const uint32_t* wb = reinterpret_cast<const uint32_t*>(sm + W2BUF);
#pragma unroll
            for (int ks = 0; ks < 16; ks++) {
                const int kk = (ks << 3) + lcb;
                uint32_t a0[4], a1[4];
                ldsm4(a0, h1Row0 + (uint32_t)((kk ^ lsw) << 2));
                ldsm4(a1, h1Row1 + (uint32_t)((kk ^ lsw) << 2));
                const int r0 = ((ks << 3) + tq) * H2D;
                const int r1 = r0 + 4 * H2D;
#pragma unroll
                for (int nt = 0; nt < 2; nt++) {
                    const int cs = (nb2 + (nt << 3)) ^ tqx;   // general XOR (bit4 collides)
                    const uint32_t b0v = wb[r0 + cs];
                    const uint32_t b1v = wb[r1 + cs];
                    mma8(c2[0][nt], a0[0], a0[1], a0[2], a0[3], b0v, b1v);
                    mma8(c2[1][nt], a1[0], a1[1], a1[2], a1[3], b0v, b1v);
                }
            }
        }
        __syncthreads();   // all done reading W2 + h1

        // h2 epilogue (overwrites W2 staging region)
        {
#pragma unroll
            for (int t = 0; t < 2; t++) {
                const int ar = mq * 32 + t * 16 + g;
                const int sw = (ar & 7) << 2;
#pragma unroll
                for (int nt = 0; nt < 2; nt++) {
                    const int colb = ng * 16 + nt * 8 + 2 * tq;
                    const float bb0 = b2[e * H2D + colb];
                    const float bb1 = b2[e * H2D + colb + 1];
                    float2 v0, v1;
                    v0.x = __uint_as_float(f2t(leaky(c2[t][nt][0] + bb0)));
                    v0.y = __uint_as_float(f2t(leaky(c2[t][nt][1] + bb1)));
                    v1.x = __uint_as_float(f2t(leaky(c2[t][nt][2] + bb0)));
                    v1.y = __uint_as_float(f2t(leaky(c2[t][nt][3] + bb1)));
                    *reinterpret_cast<float2*>(sm + H2_OFF + ar * H2D + (colb ^ sw))       = v0;
                    *reinterpret_cast<float2*>(sm + H2_OFF + (ar + 8) * H2D + (colb ^ sw)) = v1;
                }
            }
        }

        // stage W3 (full) + first Wg chunk into h1 region (h1 dead now)
        stage_tile<64, 128>(sb, W3BUF, W3s + e * 16384 + octa, ODIM, tid);
        CP_COMMIT();

        // ====== gate GEMM (B shared across both m-tiles) =======================
        float cg[2][4][4];
#pragma unroll
        for (int t = 0; t < 2; t++)
#pragma unroll
            for (int i = 0; i < 4; i++)
#pragma unroll
                for (int jj = 0; jj < 4; jj++) cg[t][i][jj] = 0.f;

        stage_tile<32, 128>(sb, WGBUF(0), Wgs + e * ODIM + octa, EO, tid);
        CP_COMMIT();

        for (int c = 0; c < 8; c++) {
            CP_WAIT0();        // waits chunk c (and W3 at c==0)
            __syncthreads();   // chunk visible; h2 writes visible (c==0)
            if (c < 7) {
                stage_tile<32, 128>(sb, WGBUF((c + 1) & 1),
                                    Wgs + ((c + 1) << 5) * EO + e * ODIM + octa, EO, tid);
                CP_COMMIT();
            }
            const uint32_t* wb = reinterpret_cast<const uint32_t*>(sm + WGBUF(c & 1));
#pragma unroll
            for (int ks = 0; ks < 4; ks++) {
                const int kk = (c << 5) + (ks << 3) + lcb;
                uint32_t a0[4], a1[4];
                ldsm4(a0, xsRow0 + (uint32_t)((kk ^ lsw) << 2));
                ldsm4(a1, xsRow1 + (uint32_t)((kk ^ lsw) << 2));
                const int r0 = ((ks << 3) + tq) * OC;
                const int r1 = r0 + 4 * OC;
#pragma unroll
                for (int nt = 0; nt < 4; nt++) {
                    const int cs = (nb1 + (nt << 3)) ^ tqx;
                    const uint32_t b0v = wb[r0 + cs];
                    const uint32_t b1v = wb[r1 + cs];
                    mma8(cg[0][nt], a0[0], a0[1], a0[2], a0[3], b0v, b1v);
                    mma8(cg[1][nt], a1[0], a1[1], a1[2], a1[3], b0v, b1v);
                }
            }
        }

        // ====== layer 3 + fold, per m-tile (caps register pressure) ============
        const uint32_t* w3 = reinterpret_cast<const uint32_t*>(sm + W3BUF);
#pragma unroll 1
        for (int t = 0; t < 2; t++) {
            float co[4][4];
#pragma unroll
            for (int i = 0; i < 4; i++)
#pragma unroll
                for (int jj = 0; jj < 4; jj++) co[i][jj] = 0.f;

            const uint32_t hRow = t ? h2Row1 : h2Row0;
#pragma unroll
            for (int ks = 0; ks < 8; ks++) {
                const int kk = (ks << 3) + lcb;
                uint32_t a[4];
                ldsm4(a, hRow + (uint32_t)((kk ^ lsw) << 2));
                const int r0 = ((ks << 3) + tq) * OC;
                const int r1 = r0 + 4 * OC;
#pragma unroll
                for (int nt = 0; nt < 4; nt++) {
                    const int cs = (nb1 + (nt << 3)) ^ tqx;
                    mma8(co[nt], a[0], a[1], a[2], a[3], w3[r0 + cs], w3[r1 + cs]);
                }
            }
            // fold: acc += exp(gate)*(o+b3); ssum += exp(gate)
#pragma unroll
            for (int nt = 0; nt < 4; nt++) {
                const int colc = octa + ng * 32 + nt * 8 + 2 * tq;
                const float bg0 = bg[e * ODIM + colc];
                const float bg1 = bg[e * ODIM + colc + 1];
                const float b30 = b3[e * ODIM + colc];
                const float b31 = b3[e * ODIM + colc + 1];
                const int ai = t * 4 + nt;
                float p;
                p = __expf(cg[t][nt][0] + bg0); acc[ai][0] += p * (co[nt][0] + b30); ssum[ai][0] += p;
                p = __expf(cg[t][nt][1] + bg1); acc[ai][1] += p * (co[nt][1] + b31); ssum[ai][1] += p;
                p = __expf(cg[t][nt][2] + bg0); acc[ai][2] += p * (co[nt][2] + b30); ssum[ai][2] += p;
                p = __expf(cg[t][nt][3] + bg1); acc[ai][3] += p * (co[nt][3] + b31); ssum[ai][3] += p;
            }
        }
        // expert-top S0 guards h2/W3/Wg region reuse
    }

    // ---- epilogue: out = acc / ssum ----
#pragma unroll
    for (int ai = 0; ai < 8; ai++) {
        const int t = ai >> 2, nt = ai & 3;
        const int colc = octa + ng * 32 + nt * 8 + 2 * tq;
        const int ar = mq * 32 + t * 16 + g;
        const size_t r0 = (size_t)(row0 + ar) * ODIM;
        const size_t r1 = (size_t)(row0 + ar + 8) * ODIM;
        float2 v0 = make_float2(acc[ai][0] / ssum[ai][0], acc[ai][1] / ssum[ai][1]);
        float2 v1 = make_float2(acc[ai][2] / ssum[ai][2], acc[ai][3] / ssum[ai][3]);
        *reinterpret_cast<float2*>(out + r0 + colc) = v0;
        *reinterpret_cast<float2*>(out + r1 + colc) = v1;
    }
}

extern "C" void kernel_launch(void* const* d_in, const int* in_sizes, int n_in,
                              void* d_out, int out_size) {
    const float* x  = (const float*)d_in[0];
    const float* W1 = (const float*)d_in[1];
    const float* b1 = (const float*)d_in[2];
    const float* W2 = (const float*)d_in[3];
    const float* b2 = (const float*)d_in[4];
    const float* W3 = (const float*)d_in[5];
    const float* b3 = (const float*)d_in[6];
    const float* Wg = (const float*)d_in[7];
    const float* bg = (const float*)d_in[8];
    float* out = (float*)d_out;
    (void)n_in; (void)out_size;

    const int B  = in_sizes[0] / LDIM;       // 65536
    const int nb = (B / BT) * 2;             // 1024 CTAs

    prep_weights<<<512, 256>>>(W1, W2, W3, Wg);

    cudaFuncSetAttribute(moe_fused_kernel,
                         cudaFuncAttributeMaxDynamicSharedMemorySize, SMEM_BYTES);
    moe_fused_kernel<<<nb, NTHREADS, SMEM_BYTES>>>(x, b1, b2, b3, bg, out);
}

// round 9
// speedup vs baseline: 2.2090x; 1.0776x over previous
#include <cuda_runtime.h>
#include <cstdint>
#include <cstddef>

// ---------------------------------------------------------------------------
// Fused MoE element-wise gating, round 9: BT=64, 256 threads, 2 CTAs/SM.
// out[b,o] = sum_e softmax_e(x@Wg+bg) * (L3(L2(L1(x)))+b3)
// B=65536, L=256, E=8, H1=128, H2=64, O=256, fp32 (tf32 mma, fp32 accum).
//
// CTA: 64 rows x 128 out-cols, 8 warps = 2 m-warps x 4 n-groups (m32n32 each).
// Warp-level GEMM inner loops identical to round 8. Weight staging aliased
// into dead h1/h2 regions; two CTAs per SM overlap each other's barriers,
// cp.async waits and epilogues to keep the tensor pipe fed.
// ---------------------------------------------------------------------------

#define BT 64
#define LDIM 256
#define ODIM 256
#define NE 8
#define H1D 128
#define H2D 64
#define EO 2048
#define OC 128
#define NTHREADS 256

// SMEM map (float words)
#define XS_OFF 0            // x tile   [64][256] swizzled          (64 KB)
#define H1_OFF 16384        // h1 tile  [64][128] / W1,Wg,W3 staging (32 KB)
#define H2_OFF 24576        // h2 tile  [64][64]  / W2 staging       (16 KB)
#define SMEM_WORDS 28672
#define SMEM_BYTES (SMEM_WORDS * 4)     // 114688

#define W1BUF(i) (H1_OFF + (i) * 4096)   // 2 x [32k x 128n]
#define W2BUF(i) (H2_OFF + (i) * 2048)   // 2 x [32k x 64n]
#define WGBUF(i) (H1_OFF + (i) * 4096)   // 2 x [32k x 128n]
#define W3BUF    H1_OFF                  // [64k x 128n] full (after gate)

// tf32-rounded weight scratch in device global memory (~3.93 MB)
#define W1S_OFF 0
#define W2S_OFF 262144
#define W3S_OFF 327680
#define WGS_OFF 458752
#define WS_TOTAL 983040
__device__ float g_ws[WS_TOTAL];

__device__ __forceinline__ uint32_t f2t(float f) {
    uint32_t u;
    asm("cvt.rna.tf32.f32 %0, %1;" : "=r"(u) : "f"(f));
    return u;
}

__device__ __forceinline__ void mma8(float c[4],
                                     uint32_t a0, uint32_t a1, uint32_t a2, uint32_t a3,
                                     uint32_t b0, uint32_t b1) {
    asm volatile(
        "mma.sync.aligned.m16n8k8.row.col.f32.tf32.tf32.f32 "
        "{%0,%1,%2,%3}, {%4,%5,%6,%7}, {%8,%9}, {%0,%1,%2,%3};"
        : "+f"(c[0]), "+f"(c[1]), "+f"(c[2]), "+f"(c[3])
        : "r"(a0), "r"(a1), "r"(a2), "r"(a3), "r"(b0), "r"(b1));
}

__device__ __forceinline__ float leaky(float v) { return v >= 0.f ? v : 0.01f * v; }

__device__ __forceinline__ void ldsm4(uint32_t a[4], uint32_t addr) {
    asm volatile("ldmatrix.sync.aligned.m8n8.x4.shared.b16 {%0,%1,%2,%3}, [%4];"
                 : "=r"(a[0]), "=r"(a[1]), "=r"(a[2]), "=r"(a[3])
                 : "r"(addr));
}

__device__ __forceinline__ void cpa16(uint32_t saddr, const float* g) {
    asm volatile("cp.async.cg.shared.global [%0], [%1], 16;" :: "r"(saddr), "l"(g));
}
#define CP_COMMIT() asm volatile("cp.async.commit_group;" ::: "memory")
#define CP_WAIT0()  asm volatile("cp.async.wait_group 0;" ::: "memory")

// Cooperative tile stage: global [R rows x W cols] -> SMEM, granule swizzle
// (n0 ^ ((r&3)<<3)); consumer uses word = r*W + (n ^ (tq<<3)).
template<int R, int W>
__device__ __forceinline__ void stage_tile(uint32_t sb, int dstWord, const float* g,
                                           int gstride, int tid) {
    constexpr int GR = W / 4;
    constexpr int TOT = R * GR;
#pragma unroll
    for (int i = 0; i < TOT; i += NTHREADS) {
        const int idx = i + tid;
        const int r = idx / GR;
        const int n0 = (idx - r * GR) << 2;
        cpa16(sb + ((dstWord + r * W + (n0 ^ ((r & 3) << 3))) << 2),
              g + (size_t)r * gstride + n0);
    }
}

// pre-round all weights to tf32 (RNA) once per launch
__global__ void prep_weights(const float* __restrict__ W1, const float* __restrict__ W2,
                             const float* __restrict__ W3, const float* __restrict__ Wg) {
    const int stride = gridDim.x * blockDim.x;
    const int i0 = blockIdx.x * blockDim.x + threadIdx.x;
    for (int i = i0; i < 262144; i += stride) g_ws[W1S_OFF + i] = __uint_as_float(f2t(W1[i]));
    for (int i = i0; i < 65536;  i += stride) g_ws[W2S_OFF + i] = __uint_as_float(f2t(W2[i]));
    for (int i = i0; i < 131072; i += stride) g_ws[W3S_OFF + i] = __uint_as_float(f2t(W3[i]));
    for (int i = i0; i < 524288; i += stride) g_ws[WGS_OFF + i] = __uint_as_float(f2t(Wg[i]));
}

__global__ void __launch_bounds__(NTHREADS, 2)
moe_fused_kernel(const float* __restrict__ x,
                 const float* __restrict__ b1, const float* __restrict__ b2,
                 const float* __restrict__ b3, const float* __restrict__ bg,
                 float* __restrict__ out) {
    extern __shared__ float sm[];
    const uint32_t sb = (uint32_t)__cvta_generic_to_shared(sm);

    const int tid  = threadIdx.x;
    const int w    = tid >> 5;
    const int lane = tid & 31;
    const int g    = lane >> 2;    // 0..7
    const int tq   = lane & 3;     // 0..3
    const int mq   = w & 1;        // m-warp: rows mq*32 .. +31 (2 m16 tiles)
    const int ng   = w >> 1;       // n-group (0..3): 32 cols

    const int btile = blockIdx.x >> 1;
    const int octa  = (blockIdx.x & 1) * OC;
    const int row0  = btile * BT;

    // ldmatrix per-lane addressing; tile0 rows = mq*32+lbase, tile1 = +16
    const int lbase = (((lane >> 3) & 1) << 3) + (lane & 7);
    const int lrow0 = mq * 32 + lbase;
    const int lrow1 = lrow0 + 16;               // same low 3 bits
    const int lsw   = (lrow0 & 7) << 2;
    const int lcb   = (lane >> 4) << 2;
    const uint32_t xsRow0 = sb + (uint32_t)((XS_OFF + lrow0 * LDIM) << 2);
    const uint32_t xsRow1 = sb + (uint32_t)((XS_OFF + lrow1 * LDIM) << 2);
    const uint32_t h1Row0 = sb + (uint32_t)((H1_OFF + lrow0 * H1D) << 2);
    const uint32_t h1Row1 = sb + (uint32_t)((H1_OFF + lrow1 * H1D) << 2);
    const uint32_t h2Row0 = sb + (uint32_t)((H2_OFF + lrow0 * H2D) << 2);
    const uint32_t h2Row1 = sb + (uint32_t)((H2_OFF + lrow1 * H2D) << 2);

    const int nb1 = ng * 32 + g;   // N=128 GEMMs (L1, gate, L3)
    const int nb2 = ng * 16 + g;   // N=64 (L2)
    const int tqx = tq << 3;       // granule swizzle XOR

    // ---- load x tile -> tf32 -> swizzled SMEM ----
    for (int i = tid; i < BT * (LDIM / 4); i += NTHREADS) {
        const int r  = i >> 6;
        const int c4 = i & 63;
        float4 v = reinterpret_cast<const float4*>(x + (size_t)(row0 + r) * LDIM)[c4];
        v.x = __uint_as_float(f2t(v.x)); v.y = __uint_as_float(f2t(v.y));
        v.z = __uint_as_float(f2t(v.z)); v.w = __uint_as_float(f2t(v.w));
        const int col = c4 * 4;
        *reinterpret_cast<float4*>(sm + XS_OFF + r * LDIM + (col ^ ((r & 7) << 2))) = v;
    }

    float acc[8][4], ssum[8][4];
#pragma unroll
    for (int i = 0; i < 8; i++)
#pragma unroll
        for (int jj = 0; jj < 4; jj++) { acc[i][jj] = 0.f; ssum[i][jj] = 0.f; }

    const float* W1s = g_ws + W1S_OFF;
    const float* W2s = g_ws + W2S_OFF;
    const float* W3s = g_ws + W3S_OFF;
    const float* Wgs = g_ws + WGS_OFF;

    for (int e = 0; e < NE; e++) {
        __syncthreads();   // S0: h1/h2 regions free (prev expert L3 done; or xs ready)

        // ================= layer 1: h1 = leaky(x @ W1_e + b1_e) ================
        stage_tile<32, 128>(sb, W1BUF(0), W1s + e * 32768, H1D, tid);
        CP_COMMIT();

        float c1[2][4][4];
#pragma unroll
        for (int t = 0; t < 2; t++)
#pragma unroll
            for (int i = 0; i < 4; i++)
#pragma unroll
                for (int jj = 0; jj < 4; jj++) c1[t][i][jj] = 0.f;

        for (int c = 0; c < 8; c++) {
            CP_WAIT0();
            __syncthreads();
            if (c < 7) {
                stage_tile<32, 128>(sb, W1BUF((c + 1) & 1),
                                    W1s + e * 32768 + ((c + 1) << 5) * H1D, H1D, tid);
                CP_COMMIT();
            }
            const uint32_t* wb = reinterpret_cast<const uint32_t*>(sm + W1BUF(c & 1));
#pragma unroll
            for (int ks = 0; ks < 4; ks++) {
                const int kk = (c << 5) + (ks << 3) + lcb;
                uint32_t a0[4], a1[4];
                ldsm4(a0, xsRow0 + (uint32_t)((kk ^ lsw) << 2));
                ldsm4(a1, xsRow1 + (uint32_t)((kk ^ lsw) << 2));
                const int r0 = ((ks << 3) + tq) * H1D;
                const int r1 = r0 + 4 * H1D;
#pragma unroll
                for (int nt = 0; nt < 4; nt++) {
                    const int cs = (nb1 + (nt << 3)) ^ tqx;
                    const uint32_t b0v = wb[r0 + cs];
                    const uint32_t b1v = wb[r1 + cs];
                    mma8(c1[0][nt], a0[0], a0[1], a0[2], a0[3], b0v, b1v);
                    mma8(c1[1][nt], a1[0], a1[1], a1[2], a1[3], b0v, b1v);
                }
            }
        }
        __syncthreads();   // all warps done reading W1 bufs (h1 region)

        // h1 epilogue -> h1 region
        {
#pragma unroll
            for (int t = 0; t < 2; t++) {
                const int ar = mq * 32 + t * 16 + g;
                const int sw = (ar & 7) << 2;
#pragma unroll
                for (int nt = 0; nt < 4; nt++) {
                    const int colb = ng * 32 + nt * 8 + 2 * tq;
                    const float bb0 = b1[e * H1D + colb];
                    const float bb1 = b1[e * H1D + colb + 1];
                    float2 v0, v1;
                    v0.x = __uint_as_float(f2t(leaky(c1[t][nt][0] + bb0)));
                    v0.y = __uint_as_float(f2t(leaky(c1[t][nt][1] + bb1)));
                    v1.x = __uint_as_float(f2t(leaky(c1[t][nt][2] + bb0)));
                    v1.y = __uint_as_float(f2t(leaky(c1[t][nt][3] + bb1)));
                    *reinterpret_cast<float2*>(sm + H1_OFF + ar * H1D + (colb ^ sw))       = v0;
                    *reinterpret_cast<float2*>(sm + H1_OFF + (ar + 8) * H1D + (colb ^ sw)) = v1;
                }
            }
        }
        __syncthreads();   // h1 visible for L2 A-reads; h2 region free for W2

        // ================= layer 2: h2 = leaky(h1 @ W2_e + b2_e) ===============
        stage_tile<32, 64>(sb, W2BUF(0), W2s + e * 8192, H2D, tid);
        CP_COMMIT();

        float c2[2][2][4];
#pragma unroll
        for (int t = 0; t < 2; t++)
#pragma unroll
            for (int i = 0; i < 2; i++)
#pragma unroll
                for (int jj = 0; jj < 4; jj++) c2[t][i][jj] = 0.f;

        for (int c = 0; c < 4; c++) {
            CP_WAIT0();
            __syncthreads();
            if (c < 3) {
                stage_tile<32, 64>(sb, W2BUF((c + 1) & 1),
                                   W2s + e * 8192 + ((c + 1) << 5) * H2D, H2D, tid);
                CP_COMMIT();
            }
            const uint32_t* wb = reinterpret_cast<const uint32_t*>(sm + W2BUF(c & 1));
#pragma unroll
            for (int ks = 0; ks < 4; ks++) {
                const int kk = (c << 5) + (ks << 3) + lcb;
                uint32_t a0[4], a1[4];
                ldsm4(a0, h1Row0 + (uint32_t)((kk ^ lsw) << 2));
                ldsm4(a1, h1Row1 + (uint32_t)((kk ^ lsw) << 2));
                const int r0 = ((ks << 3) + tq) * H2D;
                const int r1 = r0 + 4 * H2D;
#pragma unroll
                for (int nt = 0; nt < 2; nt++) {
                    const int cs = (nb2 + (nt << 3)) ^ tqx;
                    const uint32_t b0v = wb[r0 + cs];
                    const uint32_t b1v = wb[r1 + cs];
                    mma8(c2[0][nt], a0[0], a0[1], a0[2], a0[3], b0v, b1v);
                    mma8(c2[1][nt], a1[0], a1[1], a1[2], a1[3], b0v, b1v);
                }
            }
        }
        __syncthreads();   // done reading W2 bufs (h2 region) + h1 data

        // h2 epilogue -> h2 region (overwrites W2 staging)
        {
#pragma unroll
            for (int t = 0; t < 2; t++) {
                const int ar = mq * 32 + t * 16 + g;
                const int sw = (ar & 7) << 2;
#pragma unroll
                for (int nt = 0; nt < 2; nt++) {
                    const int colb = ng * 16 + nt * 8 + 2 * tq;
                    const float bb0 = b2[e * H2D + colb];
                    const float bb1 = b2[e * H2D + colb + 1];
                    float2 v0, v1;
                    v0.x = __uint_as_float(f2t(leaky(c2[t][nt][0] + bb0)));
                    v0.y = __uint_as_float(f2t(leaky(c2[t][nt][1] + bb1)));
                    v1.x = __uint_as_float(f2t(leaky(c2[t][nt][2] + bb0)));
                    v1.y = __uint_as_float(f2t(leaky(c2[t][nt][3] + bb1)));
                    *reinterpret_cast<float2*>(sm + H2_OFF + ar * H2D + (colb ^ sw))       = v0;
                    *reinterpret_cast<float2*>(sm + H2_OFF + (ar + 8) * H2D + (colb ^ sw)) = v1;
                }
            }
        }

        // ====== gate GEMM (Wg chunks through h1 region; h1 dead) ===============
        float cg[2][4][4];
#pragma unroll
        for (int t = 0; t < 2; t++)
#pragma unroll
            for (int i = 0; i < 4; i++)
#pragma unroll
                for (int jj = 0; jj < 4; jj++) cg[t][i][jj] = 0.f;

        stage_tile<32, 128>(sb, WGBUF(0), Wgs + e * ODIM + octa, EO, tid);
        CP_COMMIT();

        for (int c = 0; c < 8; c++) {
            CP_WAIT0();
            __syncthreads();   // chunk visible (c==0 also orders h2 epilogue for L3 later)
            if (c < 7) {
                stage_tile<32, 128>(sb, WGBUF((c + 1) & 1),
                                    Wgs + ((c + 1) << 5) * EO + e * ODIM + octa, EO, tid);
                CP_COMMIT();
            }
            const uint32_t* wb = reinterpret_cast<const uint32_t*>(sm + WGBUF(c & 1));
#pragma unroll
            for (int ks = 0; ks < 4; ks++) {
                const int kk = (c << 5) + (ks << 3) + lcb;
                uint32_t a0[4], a1[4];
                ldsm4(a0, xsRow0 + (uint32_t)((kk ^ lsw) << 2));
                ldsm4(a1, xsRow1 + (uint32_t)((kk ^ lsw) << 2));
                const int r0 = ((ks << 3) + tq) * OC;
                const int r1 = r0 + 4 * OC;
#pragma unroll
                for (int nt = 0; nt < 4; nt++) {
                    const int cs = (nb1 + (nt << 3)) ^ tqx;
                    const uint32_t b0v = wb[r0 + cs];
                    const uint32_t b1v = wb[r1 + cs];
                    mma8(cg[0][nt], a0[0], a0[1], a0[2], a0[3], b0v, b1v);
                    mma8(cg[1][nt], a1[0], a1[1], a1[2], a1[3], b0v, b1v);
                }
            }
        }
        __syncthreads();   // done reading Wg bufs (h1 region)

        // stage W3 full into h1 region
        stage_tile<64, 128>(sb, W3BUF, W3s + e * 16384 + octa, ODIM, tid);
        CP_COMMIT();
        CP_WAIT0();
        __syncthreads();   // W3 visible

        // ====== layer 3 + fold, per m-tile =====================================
        const uint32_t* w3 = reinterpret_cast<const uint32_t*>(sm + W3BUF);
#pragma unroll 1
        for (int t = 0; t < 2; t++) {
            float co[4][4];
#pragma unroll
            for (int i = 0; i < 4; i++)
#pragma unroll
                for (int jj = 0; jj < 4; jj++) co[i][jj] = 0.f;

            const uint32_t hRow = t ? h2Row1 : h2Row0;
#pragma unroll
            for (int ks = 0; ks < 8; ks++) {
                const int kk = (ks << 3) + lcb;
                uint32_t a[4];
                ldsm4(a, hRow + (uint32_t)((kk ^ lsw) << 2));
                const int r0 = ((ks << 3) + tq) * OC;
                const int r1 = r0 + 4 * OC;
#pragma unroll
                for (int nt = 0; nt < 4; nt++) {
                    const int cs = (nb1 + (nt << 3)) ^ tqx;
                    mma8(co[nt], a[0], a[1], a[2], a[3], w3[r0 + cs], w3[r1 + cs]);
                }
            }
            // fold: acc += exp(gate)*(o+b3); ssum += exp(gate)
#pragma unroll
            for (int nt = 0; nt < 4; nt++) {
                const int colc = octa + ng * 32 + nt * 8 + 2 * tq;
                const float bg0 = bg[e * ODIM + colc];
                const float bg1 = bg[e * ODIM + colc + 1];
                const float b30 = b3[e * ODIM + colc];
                const float b31 = b3[e * ODIM + colc + 1];
                const int ai = t * 4 + nt;
                float p;
                p = __expf(cg[t][nt][0] + bg0); acc[ai][0] += p * (co[nt][0] + b30); ssum[ai][0] += p;
                p = __expf(cg[t][nt][1] + bg1); acc[ai][1] += p * (co[nt][1] + b31); ssum[ai][1] += p;
                p = __expf(cg[t][nt][2] + bg0); acc[ai][2] += p * (co[nt][2] + b30); ssum[ai][2] += p;
                p = __expf(cg[t][nt][3] + bg1); acc[ai][3] += p * (co[nt][3] + b31); ssum[ai][3] += p;
            }
        }
        // expert-top S0 guards h1(W3)/h2 region reuse
    }

    // ---- epilogue: out = acc / ssum ----
#pragma unroll
    for (int ai = 0; ai < 8; ai++) {
        const int t = ai >> 2, nt = ai & 3;
        const int colc = octa + ng * 32 + nt * 8 + 2 * tq;
        const int ar = mq * 32 + t * 16 + g;
        const size_t r0 = (size_t)(row0 + ar) * ODIM;
        const size_t r1 = (size_t)(row0 + ar + 8) * ODIM;
        float2 v0 = make_float2(acc[ai][0] / ssum[ai][0], acc[ai][1] / ssum[ai][1]);
        float2 v1 = make_float2(acc[ai][2] / ssum[ai][2], acc[ai][3] / ssum[ai][3]);
        *reinterpret_cast<float2*>(out + r0 + colc) = v0;
        *reinterpret_cast<float2*>(out + r1 + colc) = v1;
    }
}

extern "C" void kernel_launch(void* const* d_in, const int* in_sizes, int n_in,
                              void* d_out, int out_size) {
    const float* x  = (const float*)d_in[0];
    const float* W1 = (const float*)d_in[1];
    const float* b1 = (const float*)d_in[2];
    const float* W2 = (const float*)d_in[3];
    const float* b2 = (const float*)d_in[4];
    const float* W3 = (const float*)d_in[5];
    const float* b3 = (const float*)d_in[6];
    const float* Wg = (const float*)d_in[7];
    const float* bg = (const float*)d_in[8];
    float* out = (float*)d_out;
    (void)n_in; (void)out_size;

    const int B  = in_sizes[0] / LDIM;       // 65536
    const int nb = (B / BT) * 2;             // 2048 CTAs

    prep_weights<<<512, 256>>>(W1, W2, W3, Wg);

    cudaFuncSetAttribute(moe_fused_kernel,
                         cudaFuncAttributeMaxDynamicSharedMemorySize, SMEM_BYTES);
    moe_fused_kernel<<<nb, NTHREADS, SMEM_BYTES>>>(x, b1, b2, b3, bg, out);
}

// round 12
// speedup vs baseline: 2.2777x; 1.0311x over previous
#include <cuda_runtime.h>
#include <cstdint>
#include <cstddef>

// ---------------------------------------------------------------------------
// Fused MoE element-wise gating, round 12 (byte-identical resubmit of round 11
// after infra failure): round-10 paired-k design with the lds64 ordering bug
// fixed (asm volatile + memory clobber — the non-volatile asm was hoistable
// across CP_WAIT/__syncthreads, reading stale staging data).
// out[b,o] = sum_e softmax_e(x@Wg+bg) * (L3(L2(L1(x)))+b3)
// B=65536, L=256, E=8, H1=128, H2=64, O=256, fp32 (tf32 mma, fp32 accum).
//
// CTA: 64 rows x 128 out-cols, 8 warps = 2 m-warps x 4 n-groups (m32n32).
// Weight image per [32k x N] chunk: word ((s*N+n)*4+q)*2+j = W[s*8+q+4j][n];
// lane (g,tq) fetches its (k,k+4) B pair with ONE ld.shared.v2.u32.
// ---------------------------------------------------------------------------

#define BT 64
#define LDIM 256
#define ODIM 256
#define NE 8
#define H1D 128
#define H2D 64
#define EO 2048
#define OC 128
#define NTHREADS 256

// SMEM map (float words)
#define XS_OFF 0            // x tile   [64][256] swizzled          (64 KB)
#define H1_OFF 16384        // h1 tile  [64][128] / W1,Wg,W3 staging (32 KB)
#define H2_OFF 24576        // h2 tile  [64][64]  / W2 staging       (16 KB)
#define SMEM_WORDS 28672
#define SMEM_BYTES (SMEM_WORDS * 4)     // 114688

#define W1BUF(i) (H1_OFF + (i) * 4096)   // 2 x [32k x 128n] paired-k chunks
#define W2BUF(i) (H2_OFF + (i) * 2048)   // 2 x [32k x 64n] paired-k chunks
#define WGBUF(i) (H1_OFF + (i) * 4096)   // 2 x [32k x 128n]
#define W3BUF    H1_OFF                  // 2 chunks = 8192 words (after gate)

// paired-k tf32 weight images in device scratch (word offsets)
#define W1S_OFF 0        // + e*32768 + c*4096            (c:8, N=128)
#define W2S_OFF 262144   // + e*8192  + c*2048            (c:4, N=64)
#define W3S_OFF 327680   // + e*16384 + nh*8192 + c*4096  (nh:2, c:2, N=128)
#define WGS_OFF 458752   // + e*65536 + nh*32768 + c*4096 (nh:2, c:8, N=128)
#define WS_TOTAL 983040
__device__ __align__(256) float g_ws[WS_TOTAL];

__device__ __forceinline__ uint32_t f2t(float f) {
    uint32_t u;
    asm("cvt.rna.tf32.f32 %0, %1;" : "=r"(u) : "f"(f));
    return u;
}

__device__ __forceinline__ void mma8(float c[4],
                                     uint32_t a0, uint32_t a1, uint32_t a2, uint32_t a3,
                                     uint32_t b0, uint32_t b1) {
    asm volatile(
        "mma.sync.aligned.m16n8k8.row.col.f32.tf32.tf32.f32 "
        "{%0,%1,%2,%3}, {%4,%5,%6,%7}, {%8,%9}, {%0,%1,%2,%3};"
        : "+f"(c[0]), "+f"(c[1]), "+f"(c[2]), "+f"(c[3])
        : "r"(a0), "r"(a1), "r"(a2), "r"(a3), "r"(b0), "r"(b1));
}

__device__ __forceinline__ float leaky(float v) { return v >= 0.f ? v : 0.01f * v; }

__device__ __forceinline__ void ldsm4(uint32_t a[4], uint32_t addr) {
    asm volatile("ldmatrix.sync.aligned.m8n8.x4.shared.b16 {%0,%1,%2,%3}, [%4];"
                 : "=r"(a[0]), "=r"(a[1]), "=r"(a[2]), "=r"(a[3])
                 : "r"(addr));
}

// FIX: volatile + memory clobber — must not be hoisted across
// CP_WAIT/__syncthreads that order the cp.async staging writes.
__device__ __forceinline__ uint2 lds64(uint32_t addr) {
    uint2 r;
    asm volatile("ld.shared.v2.u32 {%0,%1}, [%2];"
                 : "=r"(r.x), "=r"(r.y) : "r"(addr) : "memory");
    return r;
}

__device__ __forceinline__ void cpa16(uint32_t saddr, const float* g) {
    asm volatile("cp.async.cg.shared.global [%0], [%1], 16;" :: "r"(saddr), "l"(g));
}
#define CP_COMMIT() asm volatile("cp.async.commit_group;" ::: "memory")
#define CP_WAIT0()  asm volatile("cp.async.wait_group 0;" ::: "memory")

// linear cooperative copy; words must be a multiple of 1024 (256 thr x 16B)
__device__ __forceinline__ void stage_lin(uint32_t sb, int dstWord,
                                          const float* src, int words, int tid) {
    for (int i = tid * 4; i < words; i += NTHREADS * 4)
        cpa16(sb + (uint32_t)((dstWord + i) << 2), src + i);
}

// ---------------------------------------------------------------------------
// Prep: tf32-round + repack each [32k x N] weight tile into the paired-k
// image: word ((s*N+n)*4+q)*2+j = W[s*8+q+4j][n]. 256 blocks x 256 threads.
// ---------------------------------------------------------------------------
__global__ void prep_weights(const float* __restrict__ W1, const float* __restrict__ W2,
                             const float* __restrict__ W3, const float* __restrict__ Wg) {
    __shared__ float t[32][129];
    const int j = blockIdx.x;
    const int tid = threadIdx.x;

    const float* src;
    int stride, N, lg;
    long dst;
    if (j < 64) {                     // W1 [8e][256k][128n]: tile (e, c:8)
        const int e = j >> 3, c = j & 7;
        src = W1 + e * 32768 + c * 32 * 128; stride = 128; N = 128; lg = 7;
        dst = W1S_OFF + e * 32768 + c * 4096;
    } else if (j < 96) {              // W2 [8e][128k][64n]: tile (e, c:4)
        const int t2 = j - 64, e = t2 >> 2, c = t2 & 3;
        src = W2 + e * 8192 + c * 32 * 64; stride = 64; N = 64; lg = 6;
        dst = W2S_OFF + e * 8192 + c * 2048;
    } else if (j < 128) {             // W3 [8e][64k][256n]: tile (e, nh:2, c:2)
        const int t3 = j - 96, e = t3 >> 2, nh = (t3 >> 1) & 1, c = t3 & 1;
        src = W3 + e * 16384 + c * 32 * 256 + nh * 128; stride = 256; N = 128; lg = 7;
        dst = W3S_OFF + e * 16384 + nh * 8192 + c * 4096;
    } else {                          // Wg [256k][2048n]: tile (e, nh:2, c:8)
        const int t4 = j - 128, e = t4 >> 4, nh = (t4 >> 3) & 1, c = t4 & 7;
        src = Wg + c * 32 * EO + e * 256 + nh * 128; stride = EO; N = 128; lg = 7;
        dst = WGS_OFF + e * 65536 + nh * 32768 + c * 4096;
    }

    for (int i = tid; i < 32 * N; i += 256) {
        const int k = i >> lg, n = i & (N - 1);
        t[k][n] = __uint_as_float(f2t(src[(size_t)k * stride + n]));
    }
    __syncthreads();
    for (int idx = tid; idx < 32 * N; idx += 256) {
        const int jj = idx & 1;
        const int q  = (idx >> 1) & 3;
        const int n  = (idx >> 3) & (N - 1);
        const int s  = idx >> (3 + lg);
        g_ws[dst + idx] = t[s * 8 + q + 4 * jj][n];
    }
}

__global__ void __launch_bounds__(NTHREADS, 2)
moe_fused_kernel(const float* __restrict__ x,
                 const float* __restrict__ b1, const float* __restrict__ b2,
                 const float* __restrict__ b3, const float* __restrict__ bg,
                 float* __restrict__ out) {
    extern __shared__ float sm[];
    const uint32_t sb = (uint32_t)__cvta_generic_to_shared(sm);

    const int tid  = threadIdx.x;
    const int w    = tid >> 5;
    const int lane = tid & 31;
    const int g    = lane >> 2;    // 0..7
    const int tq   = lane & 3;     // 0..3
    const int mq   = w & 1;        // m-warp: rows mq*32 .. +31 (2 m16 tiles)
    const int ng   = w >> 1;       // n-group (0..3): 32 cols

    const int btile = blockIdx.x >> 1;
    const int octa  = (blockIdx.x & 1) * OC;
    const int row0  = btile * BT;

    // ldmatrix per-lane addressing
    const int lbase = (((lane >> 3) & 1) << 3) + (lane & 7);
    const int lrow0 = mq * 32 + lbase;
    const int lrow1 = lrow0 + 16;
    const int lsw   = (lrow0 & 7) << 2;
    const int lcb   = (lane >> 4) << 2;
    const uint32_t xsRow0 = sb + (uint32_t)((XS_OFF + lrow0 * LDIM) << 2);
    const uint32_t xsRow1 = sb + (uint32_t)((XS_OFF + lrow1 * LDIM) << 2);
    const uint32_t h1Row0 = sb + (uint32_t)((H1_OFF + lrow0 * H1D) << 2);
    const uint32_t h1Row1 = sb + (uint32_t)((H1_OFF + lrow1 * H1D) << 2);
    const uint32_t h2Row0 = sb + (uint32_t)((H2_OFF + lrow0 * H2D) << 2);
    const uint32_t h2Row1 = sb + (uint32_t)((H2_OFF + lrow1 * H2D) << 2);

    // paired-k B addressing: byte = ((s*N + nb + nt*8)*8 + tq*2) * 4
    const int nb1 = ng * 32 + g;   // N=128 GEMMs (L1, gate, L3)
    const int nb2 = ng * 16 + g;   // N=64 (L2)
    const int bq  = tq * 2;        // pair word offset

    // ---- load x tile -> tf32 -> swizzled SMEM ----
    for (int i = tid; i < BT * (LDIM / 4); i += NTHREADS) {
        const int r  = i >> 6;
        const int c4 = i & 63;
        float4 v = reinterpret_cast<const float4*>(x + (size_t)(row0 + r) * LDIM)[c4];
        v.x = __uint_as_float(f2t(v.x)); v.y = __uint_as_float(f2t(v.y));
        v.z = __uint_as_float(f2t(v.z)); v.w = __uint_as_float(f2t(v.w));
        const int col = c4 * 4;
        *reinterpret_cast<float4*>(sm + XS_OFF + r * LDIM + (col ^ ((r & 7) << 2))) = v;
    }

    float acc[8][4], ssum[8][4];
#pragma unroll
    for (int i = 0; i < 8; i++)
#pragma unroll
        for (int jj = 0; jj < 4; jj++) { acc[i][jj] = 0.f; ssum[i][jj] = 0.f; }

    for (int e = 0; e < NE; e++) {
        const float* w1i = g_ws + W1S_OFF + e * 32768;
        const float* w2i = g_ws + W2S_OFF + e * 8192;
        const float* w3i = g_ws + W3S_OFF + e * 16384 + (octa ? 8192 : 0);
        const float* wgi = g_ws + WGS_OFF + e * 65536 + (octa ? 32768 : 0);

        __syncthreads();   // S0: h1/h2 regions free

        // ================= layer 1: h1 = leaky(x @ W1_e + b1_e) ================
        stage_lin(sb, W1BUF(0), w1i, 4096, tid);
        CP_COMMIT();

        float c1[2][4][4];
#pragma unroll
        for (int t = 0; t < 2; t++)
#pragma unroll
            for (int i = 0; i < 4; i++)
#pragma unroll
                for (int jj = 0; jj < 4; jj++) c1[t][i][jj] = 0.f;

        for (int c = 0; c < 8; c++) {
            CP_WAIT0();
            __syncthreads();
            if (c < 7) {
                stage_lin(sb, W1BUF((c + 1) & 1), w1i + (c + 1) * 4096, 4096, tid);
                CP_COMMIT();
            }
            const uint32_t wb = sb + (uint32_t)(W1BUF(c & 1) << 2);
#pragma unroll
            for (int s = 0; s < 4; s++) {
                const int kk = (c << 5) + (s << 3) + lcb;
                uint32_t a0[4], a1[4];
                ldsm4(a0, xsRow0 + (uint32_t)((kk ^ lsw) << 2));
                ldsm4(a1, xsRow1 + (uint32_t)((kk ^ lsw) << 2));
                uint2 bp[4];
#pragma unroll
                for (int nt = 0; nt < 4; nt++)
                    bp[nt] = lds64(wb + (uint32_t)((((s * 128 + nb1 + nt * 8) << 3) + bq) << 2));
#pragma unroll
                for (int nt = 0; nt < 4; nt++) {
                    mma8(c1[0][nt], a0[0], a0[1], a0[2], a0[3], bp[nt].x, bp[nt].y);
                    mma8(c1[1][nt], a1[0], a1[1], a1[2], a1[3], bp[nt].x, bp[nt].y);
                }
            }
        }
        __syncthreads();   // all warps done reading W1 bufs (h1 region)

        // h1 epilogue -> h1 region
        {
#pragma unroll
            for (int t = 0; t < 2; t++) {
                const int ar = mq * 32 + t * 16 + g;
                const int sw = (ar & 7) << 2;
#pragma unroll
                for (int nt = 0; nt < 4; nt++) {
                    const int colb = ng * 32 + nt * 8 + 2 * tq;
                    const float bb0 = b1[e * H1D + colb];
                    const float bb1 = b1[e * H1D + colb + 1];
                    float2 v0, v1;
                    v0.x = __uint_as_float(f2t(leaky(c1[t][nt][0] + bb0)));
                    v0.y = __uint_as_float(f2t(leaky(c1[t][nt][1] + bb1)));
                    v1.x = __uint_as_float(f2t(leaky(c1[t][nt][2] + bb0)));
                    v1.y = __uint_as_float(f2t(leaky(c1[t][nt][3] + bb1)));
                    *reinterpret_cast<float2*>(sm + H1_OFF + ar * H1D + (colb ^ sw))       = v0;
                    *reinterpret_cast<float2*>(sm + H1_OFF + (ar + 8) * H1D + (colb ^ sw)) = v1;
                }
            }
        }
        __syncthreads();   // h1 visible; h2 region free for W2

        // ================= layer 2: h2 = leaky(h1 @ W2_e + b2_e) ===============
        stage_lin(sb, W2BUF(0), w2i, 2048, tid);
        CP_COMMIT();

        float c2[2][2][4];
#pragma unroll
        for (int t = 0; t < 2; t++)
#pragma unroll
            for (int i = 0; i < 2; i++)
#pragma unroll
                for (int jj = 0; jj < 4; jj++) c2[t][i][jj] = 0.f;

        for (int c = 0; c < 4; c++) {
            CP_WAIT0();
            __syncthreads();
            if (c < 3) {
                stage_lin(sb, W2BUF((c + 1) & 1), w2i + (c + 1) * 2048, 2048, tid);
                CP_COMMIT();
            }
            const uint32_t wb = sb + (uint32_t)(W2BUF(c & 1) << 2);
#pragma unroll
            for (int s = 0; s < 4; s++) {
                const int kk = (c << 5) + (s << 3) + lcb;
                uint32_t a0[4], a1[4];
                ldsm4(a0, h1Row0 + (uint32_t)((kk ^ lsw) << 2));
                ldsm4(a1, h1Row1 + (uint32_t)((kk ^ lsw) << 2));
                uint2 bp[2];
#pragma unroll
                for (int nt = 0; nt < 2; nt++)
                    bp[nt] = lds64(wb + (uint32_t)((((s * 64 + nb2 + nt * 8) << 3) + bq) << 2));
#pragma unroll
                for (int nt = 0; nt < 2; nt++) {
                    mma8(c2[0][nt], a0[0], a0[1], a0[2], a0[3], bp[nt].x, bp[nt].y);
                    mma8(c2[1][nt], a1[0], a1[1], a1[2], a1[3], bp[nt].x, bp[nt].y);
                }
            }
        }
        __syncthreads();   // done reading W2 bufs (h2 region) + h1 data

        // h2 epilogue -> h2 region (overwrites W2 staging)
        {
#pragma unroll
            for (int t = 0; t < 2; t++) {
                const int ar = mq * 32 + t * 16 + g;
                const int sw = (ar & 7) << 2;
#pragma unroll
                for (int nt = 0; nt < 2; nt++) {
                    const int colb = ng * 16 + nt * 8 + 2 * tq;
                    const float bb0 = b2[e * H2D + colb];
                    const float bb1 = b2[e * H2D + colb + 1];
                    float2 v0, v1;
                    v0.x = __uint_as_float(f2t(leaky(c2[t][nt][0] + bb0)));
                    v0.y = __uint_as_float(f2t(leaky(c2[t][nt][1] + bb1)));
                    v1.x = __uint_as_float(f2t(leaky(c2[t][nt][2] + bb0)));
                    v1.y = __uint_as_float(f2t(leaky(c2[t][nt][3] + bb1)));
                    *reinterpret_cast<float2*>(sm + H2_OFF + ar * H2D + (colb ^ sw))       = v0;
                    *reinterpret_cast<float2*>(sm + H2_OFF + (ar + 8) * H2D + (colb ^ sw)) = v1;
                }
            }
        }

        // ====== gate GEMM (Wg chunks through h1 region; h1 dead) ===============
        float cg[2][4][4];
#pragma unroll
        for (int t = 0; t < 2; t++)
#pragma unroll
            for (int i = 0; i < 4; i++)
#pragma unroll
                for (int jj = 0; jj < 4; jj++) cg[t][i][jj] = 0.f;

        stage_lin(sb, WGBUF(0), wgi, 4096, tid);
        CP_COMMIT();

        for (int c = 0; c < 8; c++) {
            CP_WAIT0();
            __syncthreads();
            if (c < 7) {
                stage_lin(sb, WGBUF((c + 1) & 1), wgi + (c + 1) * 4096, 4096, tid);
                CP_COMMIT();
            }
            const uint32_t wb = sb + (uint32_t)(WGBUF(c & 1) << 2);
#pragma unroll
            for (int s = 0; s < 4; s++) {
                const int kk = (c << 5) + (s << 3) + lcb;
                uint32_t a0[4], a1[4];
                ldsm4(a0, xsRow0 + (uint32_t)((kk ^ lsw) << 2));
                ldsm4(a1, xsRow1 + (uint32_t)((kk ^ lsw) << 2));
                uint2 bp[4];
#pragma unroll
                for (int nt = 0; nt < 4; nt++)
                    bp[nt] = lds64(wb + (uint32_t)((((s * 128 + nb1 + nt * 8) << 3) + bq) << 2));
#pragma unroll
                for (int nt = 0; nt < 4; nt++) {
                    mma8(cg[0][nt], a0[0], a0[1], a0[2], a0[3], bp[nt].x, bp[nt].y);
                    mma8(cg[1][nt], a1[0], a1[1], a1[2], a1[3], bp[nt].x, bp[nt].y);
                }
            }
        }
        __syncthreads();   // done reading Wg bufs (h1 region)

        // stage W3 full (2 chunks = 8192 words) into h1 region
        stage_lin(sb, W3BUF, w3i, 8192, tid);
        CP_COMMIT();
        CP_WAIT0();
        __syncthreads();   // W3 visible

        // ====== layer 3 + fold, per m-tile =====================================
#pragma unroll 1
        for (int t = 0; t < 2; t++) {
            float co[4][4];
#pragma unroll
            for (int i = 0; i < 4; i++)
#pragma unroll
                for (int jj = 0; jj < 4; jj++) co[i][jj] = 0.f;

            const uint32_t hRow = t ? h2Row1 : h2Row0;
#pragma unroll
            for (int ks = 0; ks < 8; ks++) {
                const int kk = (ks << 3) + lcb;
                uint32_t a[4];
                ldsm4(a, hRow + (uint32_t)((kk ^ lsw) << 2));
                const uint32_t wb = sb + (uint32_t)((W3BUF + (ks >> 2) * 4096) << 2);
                const int s3 = ks & 3;
                uint2 bp[4];
#pragma unroll
                for (int nt = 0; nt < 4; nt++)
                    bp[nt] = lds64(wb + (uint32_t)((((s3 * 128 + nb1 + nt * 8) << 3) + bq) << 2));
#pragma unroll
                for (int nt = 0; nt < 4; nt++)
                    mma8(co[nt], a[0], a[1], a[2], a[3], bp[nt].x, bp[nt].y);
            }
            // fold: acc += exp(gate)*(o+b3); ssum += exp(gate)
#pragma unroll
            for (int nt = 0; nt < 4; nt++) {
                const int colc = octa + ng * 32 + nt * 8 + 2 * tq;
                const float bg0 = bg[e * ODIM + colc];
                const float bg1 = bg[e * ODIM + colc + 1];
                const float b30 = b3[e * ODIM + colc];
                const float b31 = b3[e * ODIM + colc + 1];
                const int ai = t * 4 + nt;
                float p;
                p = __expf(cg[t][nt][0] + bg0); acc[ai][0] += p * (co[nt][0] + b30); ssum[ai][0] += p;
                p = __expf(cg[t][nt][1] + bg1); acc[ai][1] += p * (co[nt][1] + b31); ssum[ai][1] += p;
                p = __expf(cg[t][nt][2] + bg0); acc[ai][2] += p * (co[nt][2] + b30); ssum[ai][2] += p;
                p = __expf(cg[t][nt][3] + bg1); acc[ai][3] += p * (co[nt][3] + b31); ssum[ai][3] += p;
            }
        }
        // expert-top S0 guards h1(W3)/h2 region reuse
    }

    // ---- epilogue: out = acc / ssum ----
#pragma unroll
    for (int ai = 0; ai < 8; ai++) {
        const int t = ai >> 2, nt = ai & 3;
        const int colc = octa + ng * 32 + nt * 8 + 2 * tq;
        const int ar = mq * 32 + t * 16 + g;
        const size_t r0 = (size_t)(row0 + ar) * ODIM;
        const size_t r1 = (size_t)(row0 + ar + 8) * ODIM;
        float2 v0 = make_float2(acc[ai][0] / ssum[ai][0], acc[ai][1] / ssum[ai][1]);
        float2 v1 = make_float2(acc[ai][2] / ssum[ai][2], acc[ai][3] / ssum[ai][3]);
        *reinterpret_cast<float2*>(out + r0 + colc) = v0;
        *reinterpret_cast<float2*>(out + r1 + colc) = v1;
    }
}

extern "C" void kernel_launch(void* const* d_in, const int* in_sizes, int n_in,
                              void* d_out, int out_size) {
    const float* x  = (const float*)d_in[0];
    const float* W1 = (const float*)d_in[1];
    const float* b1 = (const float*)d_in[2];
    const float* W2 = (const float*)d_in[3];
    const float* b2 = (const float*)d_in[4];
    const float* W3 = (const float*)d_in[5];
    const float* b3 = (const float*)d_in[6];
    const float* Wg = (const float*)d_in[7];
    const float* bg = (const float*)d_in[8];
    float* out = (float*)d_out;
    (void)n_in; (void)out_size;

    const int B  = in_sizes[0] / LDIM;       // 65536
    const int nb = (B / BT) * 2;             // 2048 CTAs

    prep_weights<<<256, 256>>>(W1, W2, W3, Wg);

    cudaFuncSetAttribute(moe_fused_kernel,
                         cudaFuncAttributeMaxDynamicSharedMemorySize, SMEM_BYTES);
    moe_fused_kernel<<<nb, NTHREADS, SMEM_BYTES>>>(x, b1, b2, b3, bg, out);
}